// round 2
// baseline (speedup 1.0000x reference)
#include <cuda_runtime.h>

// Problem constants (fixed shapes for this problem)
#define BXN 128     // batch of X paths (i)
#define BYN 128     // batch of Y paths (j)
#define TN  1024    // time points
#define DN  64      // path dimension
#define NSTEPS 1023 // TN-1
#define CL  16      // outputs (t values) per chunk
#define NC  64      // chunks (CL*NC == TN)
#define TI  32      // CTA tile in i
#define TJ  32      // CTA tile in j
#define NTHREADS 64

// Scratch (no allocation allowed -> device globals)
__device__ float g_Cprod[NC * BXN * BYN];  // per-chunk total product
__device__ float g_Pexc [NC * BXN * BYN];  // exclusive prefix product per chunk

// ---------------------------------------------------------------------------
// K1: per-chunk local cumulative products.
// Grid (4,4,NC). CTA = 64 threads handling a 32x32 (i,j) tile over CL=16 t's.
// Each thread owns a 4x4 sub-tile. dX/dY are formed on the fly (prev rows kept
// in registers), stored transposed [d][row] in smem for conflict-free LDS.128.
// Local cumprods are staged in smem and flushed as contiguous 4-float t-runs.
// ---------------------------------------------------------------------------
__launch_bounds__(NTHREADS)
__global__ void k1_chunk(const float* __restrict__ X,
                         const float* __restrict__ Y,
                         float* __restrict__ out)
{
    const int i0    = blockIdx.x * TI;
    const int j0    = blockIdx.y * TJ;
    const int c     = blockIdx.z;
    const int tbase = c * CL;

    __shared__ float dxs[DN][36];        // [d][i], padded row (144B, 16B aligned)
    __shared__ float dys[DN][36];        // [d][j]
    __shared__ float staging[4][TI*TJ];  // 4 t-slots x 1024 pairs

    const int tid = threadIdx.x;
    const int tx  = tid & 7;    // j-group (4 j's)
    const int ty  = tid >> 3;   // i-group (4 i's)
    const int r   = tid & 31;   // loader row
    const int h   = tid >> 5;   // loader d-half (0 or 1)

    const float STEP = 1.0f / 1023.0f;   // matches jnp.linspace delta in fp32

    const float* Xrow = X + ((size_t)(i0 + r) * TN + tbase) * DN + h * 32;
    const float* Yrow = Y + ((size_t)(j0 + r) * TN + tbase) * DN + h * 32;

    // previous-time rows held in registers (32 floats X + 32 floats Y / thread)
    float4 xp[8], yp[8];
#pragma unroll
    for (int q = 0; q < 8; q++) {
        xp[q] = *(const float4*)(Xrow + q * 4);
        yp[q] = *(const float4*)(Yrow + q * 4);
    }

    float K[4][4];
#pragma unroll
    for (int a = 0; a < 4; a++)
#pragma unroll
        for (int b = 0; b < 4; b++) K[a][b] = 1.0f;

    for (int k = 0; k < CL; k++) {
        const int s = tbase + k;

        // ---- stage current K (this is out[t = tbase+k] / chunk-prefix) ----
        const int slot = k & 3;
#pragma unroll
        for (int a = 0; a < 4; a++) {
            float4 v = make_float4(K[a][0], K[a][1], K[a][2], K[a][3]);
            *(float4*)&staging[slot][(ty * 4 + a) * TJ + tx * 4] = v;
        }

        // ---- flush staged 4 t-values as contiguous runs ----
        if (slot == 3) {
            __syncthreads();
            const int tflush = tbase + k - 3;
#pragma unroll
            for (int w = 0; w < 16; w++) {
                int p  = tid + NTHREADS * w;     // pair index in tile
                int pi = p >> 5, pj = p & 31;
                float4 v = make_float4(staging[0][p], staging[1][p],
                                       staging[2][p], staging[3][p]);
                *(float4*)(out + ((size_t)(i0 + pi) * BYN + (j0 + pj)) * TN + tflush) = v;
            }
            __syncthreads();
        }

        if (s < NSTEPS) {
            // ---- load next-time rows, form increments into transposed smem ----
            float4 xn[8], yn[8];
            const float* Xr = Xrow + (size_t)(k + 1) * DN;
            const float* Yr = Yrow + (size_t)(k + 1) * DN;
#pragma unroll
            for (int q = 0; q < 8; q++) {
                xn[q] = *(const float4*)(Xr + q * 4);
                yn[q] = *(const float4*)(Yr + q * 4);
            }
            __syncthreads();   // previous d-loop readers done
#pragma unroll
            for (int q = 0; q < 8; q++) {
                const int d0 = h * 32 + q * 4;
                dxs[d0 + 0][r] = xn[q].x - xp[q].x;
                dxs[d0 + 1][r] = xn[q].y - xp[q].y;
                dxs[d0 + 2][r] = xn[q].z - xp[q].z;
                dxs[d0 + 3][r] = xn[q].w - xp[q].w;
                dys[d0 + 0][r] = yn[q].x - yp[q].x;
                dys[d0 + 1][r] = yn[q].y - yp[q].y;
                dys[d0 + 2][r] = yn[q].z - yp[q].z;
                dys[d0 + 3][r] = yn[q].w - yp[q].w;
                xp[q] = xn[q];
                yp[q] = yn[q];
            }
            __syncthreads();

            // dt exactly as jnp.linspace: t_k = k*STEP (fp32), endpoint = 1.0f
            const float t1  = (s + 1 == NSTEPS) ? 1.0f : (float)(s + 1) * STEP;
            const float t0  = (float)s * STEP;
            const float inv = 1.0f / (t1 - t0);

            // ---- 32x32x64 dot tile: 16 FMA + 2 LDS.128 per warp-d ----
            float acc[4][4];
#pragma unroll
            for (int a = 0; a < 4; a++)
#pragma unroll
                for (int b = 0; b < 4; b++) acc[a][b] = 0.0f;

#pragma unroll
            for (int d = 0; d < DN; d++) {
                const float4 xa = *(const float4*)&dxs[d][ty * 4];
                const float4 yb = *(const float4*)&dys[d][tx * 4];
                acc[0][0] = fmaf(xa.x, yb.x, acc[0][0]);
                acc[0][1] = fmaf(xa.x, yb.y, acc[0][1]);
                acc[0][2] = fmaf(xa.x, yb.z, acc[0][2]);
                acc[0][3] = fmaf(xa.x, yb.w, acc[0][3]);
                acc[1][0] = fmaf(xa.y, yb.x, acc[1][0]);
                acc[1][1] = fmaf(xa.y, yb.y, acc[1][1]);
                acc[1][2] = fmaf(xa.y, yb.z, acc[1][2]);
                acc[1][3] = fmaf(xa.y, yb.w, acc[1][3]);
                acc[2][0] = fmaf(xa.z, yb.x, acc[2][0]);
                acc[2][1] = fmaf(xa.z, yb.y, acc[2][1]);
                acc[2][2] = fmaf(xa.z, yb.z, acc[2][2]);
                acc[2][3] = fmaf(xa.z, yb.w, acc[2][3]);
                acc[3][0] = fmaf(xa.w, yb.x, acc[3][0]);
                acc[3][1] = fmaf(xa.w, yb.y, acc[3][1]);
                acc[3][2] = fmaf(xa.w, yb.z, acc[3][2]);
                acc[3][3] = fmaf(xa.w, yb.w, acc[3][3]);
            }

            // ---- scan update: K *= (1 + g) ----
#pragma unroll
            for (int a = 0; a < 4; a++)
#pragma unroll
                for (int b = 0; b < 4; b++)
                    K[a][b] *= fmaf(acc[a][b], inv, 1.0f);
        }
    }

    // chunk-total product (for cross-chunk prefix)
    float* Cp = g_Cprod + (size_t)c * (BXN * BYN);
#pragma unroll
    for (int a = 0; a < 4; a++) {
        float4 v = make_float4(K[a][0], K[a][1], K[a][2], K[a][3]);
        *(float4*)&Cp[(i0 + ty * 4 + a) * BYN + (j0 + tx * 4)] = v;
    }
}

// ---------------------------------------------------------------------------
// K2: exclusive prefix product across the NC chunks, per (i,j) pair. Tiny.
// ---------------------------------------------------------------------------
__global__ void k2_prefix()
{
    const int p = blockIdx.x * blockDim.x + threadIdx.x;
    if (p >= BXN * BYN) return;
    float run = 1.0f;
#pragma unroll
    for (int c = 0; c < NC; c++) {
        const float v = g_Cprod[c * BXN * BYN + p];
        g_Pexc[c * BXN * BYN + p] = run;
        run *= v;
    }
}

// ---------------------------------------------------------------------------
// K3: out[i,j,t] *= Pexc[chunk(t), i, j]  (streaming float4 rescale)
// ---------------------------------------------------------------------------
__global__ void k3_scale(float* __restrict__ out)
{
    const size_t v = (size_t)blockIdx.x * blockDim.x + threadIdx.x;
    const size_t e = v * 4;              // element index
    const int pair = (int)(e >> 10);     // / TN
    const int t    = (int)(e & (TN - 1));
    const int c    = t >> 4;             // / CL (CL == 16)
    const float pf = g_Pexc[c * BXN * BYN + pair];
    float4 val = ((float4*)out)[v];
    val.x *= pf; val.y *= pf; val.z *= pf; val.w *= pf;
    ((float4*)out)[v] = val;
}

extern "C" void kernel_launch(void* const* d_in, const int* in_sizes, int n_in,
                              void* d_out, int out_size)
{
    const float* X = (const float*)d_in[0];
    const float* Y = (const float*)d_in[1];
    float* out = (float*)d_out;

    dim3 g1(BXN / TI, BYN / TJ, NC);     // 4 x 4 x 64 = 1024 CTAs
    k1_chunk<<<g1, NTHREADS>>>(X, Y, out);

    k2_prefix<<<(BXN * BYN + 255) / 256, 256>>>();

    const int nvec = BXN * BYN * TN / 4; // 4M float4
    k3_scale<<<(nvec + 255) / 256, 256>>>(out);
}

// round 4
// speedup vs baseline: 1.0200x; 1.0200x over previous
#include <cuda_runtime.h>

// Problem constants (fixed shapes for this problem)
#define BXN 128     // batch of X paths (i)
#define BYN 128     // batch of Y paths (j)
#define TN  1024    // time points
#define DN  64      // path dimension
#define NSTEPS 1023 // TN-1
#define CL  16      // outputs (t values) per chunk
#define NC  64      // chunks (CL*NC == TN)
#define TI  32      // CTA tile in i
#define TJ  32      // CTA tile in j
#define NTHREADS 64

// Scratch (no allocation allowed -> device globals)
__device__ float g_Cprod[NC * BXN * BYN];  // per-chunk total product
__device__ float g_Pexc [NC * BXN * BYN];  // exclusive prefix product per chunk

// ---------------------------------------------------------------------------
// K1: per-chunk local cumulative products, software-pipelined.
// Grid (4,4,NC). CTA = 64 threads, 32x32 (i,j) tile, CL=16 sequential t-steps.
// Pipeline per step k:
//   1. stage K(t=s) to smem staging
//   2. issue LDG for rows s+2 (consumed only at phase 6 -> latency hidden
//      behind the 1024-FFMA dot phase)
//   3. FMA dot over smem increments of step k, K *= (1 + g/dt)
//   4. barrier  (increment readers done; staging visible)
//   5. every 4th step: flush 4 staged t-slices as contiguous float4 runs
//   6. STS increments for step k+1 (nxt - cur), rotate cur<-nxt
//   7. barrier  (increments visible before next FMA; also orders flush reads
//      of staging before next iteration's staging writes)
// ---------------------------------------------------------------------------
__launch_bounds__(NTHREADS)
__global__ void k1_chunk(const float* __restrict__ X,
                         const float* __restrict__ Y,
                         float* __restrict__ out)
{
    const int i0    = blockIdx.x * TI;
    const int j0    = blockIdx.y * TJ;
    const int c     = blockIdx.z;
    const int tbase = c * CL;

    __shared__ float dxs[DN][36];        // [d][i], padded row
    __shared__ float dys[DN][36];        // [d][j]
    __shared__ float staging[4][TI*TJ];  // 4 t-slots x 1024 pairs

    const int tid = threadIdx.x;
    const int tx  = tid & 7;    // j-group (4 j's)
    const int ty  = tid >> 3;   // i-group (4 i's)
    const int r   = tid & 31;   // loader row
    const int h   = tid >> 5;   // loader d-half (0 or 1)

    const float STEP = 1.0f / 1023.0f;   // matches jnp.linspace delta in fp32

    const float* Xrow = X + ((size_t)(i0 + r) * TN + tbase) * DN + h * 32;
    const float* Yrow = Y + ((size_t)(j0 + r) * TN + tbase) * DN + h * 32;

    // cur = row (tbase+1) after prologue; nxt = incoming row
    float4 curX[8], curY[8], nxtX[8], nxtY[8];

    // ---- prologue: rows tbase and tbase+1, increments for step tbase ----
#pragma unroll
    for (int q = 0; q < 8; q++) {
        float4 p0 = *(const float4*)(Xrow + q * 4);
        float4 p1 = *(const float4*)(Xrow + DN + q * 4);
        float4 q0 = *(const float4*)(Yrow + q * 4);
        float4 q1 = *(const float4*)(Yrow + DN + q * 4);
        const int d0 = h * 32 + q * 4;
        dxs[d0 + 0][r] = p1.x - p0.x;
        dxs[d0 + 1][r] = p1.y - p0.y;
        dxs[d0 + 2][r] = p1.z - p0.z;
        dxs[d0 + 3][r] = p1.w - p0.w;
        dys[d0 + 0][r] = q1.x - q0.x;
        dys[d0 + 1][r] = q1.y - q0.y;
        dys[d0 + 2][r] = q1.z - q0.z;
        dys[d0 + 3][r] = q1.w - q0.w;
        curX[q] = p1; curY[q] = q1;
    }
    __syncthreads();

    float K[4][4];
#pragma unroll
    for (int a = 0; a < 4; a++)
#pragma unroll
        for (int b = 0; b < 4; b++) K[a][b] = 1.0f;

#pragma unroll 1
    for (int k = 0; k < CL; k++) {
        const int s    = tbase + k;
        const int slot = k & 3;

        // ---- 1. stage current K (value of out[t = s] before chunk prefix) ----
#pragma unroll
        for (int a = 0; a < 4; a++) {
            float4 v = make_float4(K[a][0], K[a][1], K[a][2], K[a][3]);
            *(float4*)&staging[slot][(ty * 4 + a) * TJ + tx * 4] = v;
        }

        // ---- 2. prefetch rows s+2 (consumer is phase 6, after the FMA loop) --
        if (s + 2 < TN) {
            const float* Xr = Xrow + (size_t)(k + 2) * DN;
            const float* Yr = Yrow + (size_t)(k + 2) * DN;
#pragma unroll
            for (int q = 0; q < 8; q++) {
                nxtX[q] = *(const float4*)(Xr + q * 4);
                nxtY[q] = *(const float4*)(Yr + q * 4);
            }
        }

        // ---- 3. dot phase + scan update ----
        if (s < NSTEPS) {
            const float t1  = (s + 1 == NSTEPS) ? 1.0f : (float)(s + 1) * STEP;
            const float t0  = (float)s * STEP;
            const float inv = 1.0f / (t1 - t0);

            float acc[4][4];
#pragma unroll
            for (int a = 0; a < 4; a++)
#pragma unroll
                for (int b = 0; b < 4; b++) acc[a][b] = 0.0f;

#pragma unroll 16
            for (int d = 0; d < DN; d++) {
                const float4 xa = *(const float4*)&dxs[d][ty * 4];
                const float4 yb = *(const float4*)&dys[d][tx * 4];
                acc[0][0] = fmaf(xa.x, yb.x, acc[0][0]);
                acc[0][1] = fmaf(xa.x, yb.y, acc[0][1]);
                acc[0][2] = fmaf(xa.x, yb.z, acc[0][2]);
                acc[0][3] = fmaf(xa.x, yb.w, acc[0][3]);
                acc[1][0] = fmaf(xa.y, yb.x, acc[1][0]);
                acc[1][1] = fmaf(xa.y, yb.y, acc[1][1]);
                acc[1][2] = fmaf(xa.y, yb.z, acc[1][2]);
                acc[1][3] = fmaf(xa.y, yb.w, acc[1][3]);
                acc[2][0] = fmaf(xa.z, yb.x, acc[2][0]);
                acc[2][1] = fmaf(xa.z, yb.y, acc[2][1]);
                acc[2][2] = fmaf(xa.z, yb.z, acc[2][2]);
                acc[2][3] = fmaf(xa.z, yb.w, acc[2][3]);
                acc[3][0] = fmaf(xa.w, yb.x, acc[3][0]);
                acc[3][1] = fmaf(xa.w, yb.y, acc[3][1]);
                acc[3][2] = fmaf(xa.w, yb.z, acc[3][2]);
                acc[3][3] = fmaf(xa.w, yb.w, acc[3][3]);
            }

#pragma unroll
            for (int a = 0; a < 4; a++)
#pragma unroll
                for (int b = 0; b < 4; b++)
                    K[a][b] *= fmaf(acc[a][b], inv, 1.0f);
        }

        // ---- 4. barrier: increment readers + staging writers retired ----
        __syncthreads();

        // ---- 5. flush 4 staged t-slices as contiguous runs ----
        if (slot == 3) {
            const int tflush = tbase + k - 3;
#pragma unroll
            for (int w = 0; w < 16; w++) {
                int p  = tid + NTHREADS * w;     // pair index in tile
                int pi = p >> 5, pj = p & 31;
                float4 v = make_float4(staging[0][p], staging[1][p],
                                       staging[2][p], staging[3][p]);
                *(float4*)(out + ((size_t)(i0 + pi) * BYN + (j0 + pj)) * TN + tflush) = v;
            }
        }

        // ---- 6. increments for step k+1 from prefetched rows ----
        if (k + 1 < CL && s + 1 < NSTEPS) {
#pragma unroll
            for (int q = 0; q < 8; q++) {
                const int d0 = h * 32 + q * 4;
                dxs[d0 + 0][r] = nxtX[q].x - curX[q].x;
                dxs[d0 + 1][r] = nxtX[q].y - curX[q].y;
                dxs[d0 + 2][r] = nxtX[q].z - curX[q].z;
                dxs[d0 + 3][r] = nxtX[q].w - curX[q].w;
                dys[d0 + 0][r] = nxtY[q].x - curY[q].x;
                dys[d0 + 1][r] = nxtY[q].y - curY[q].y;
                dys[d0 + 2][r] = nxtY[q].z - curY[q].z;
                dys[d0 + 3][r] = nxtY[q].w - curY[q].w;
                curX[q] = nxtX[q];
                curY[q] = nxtY[q];
            }
        }

        // ---- 7. barrier: increments visible; staging safe to overwrite ----
        __syncthreads();
    }

    // chunk-total product (for cross-chunk prefix)
    float* Cp = g_Cprod + (size_t)c * (BXN * BYN);
#pragma unroll
    for (int a = 0; a < 4; a++) {
        float4 v = make_float4(K[a][0], K[a][1], K[a][2], K[a][3]);
        *(float4*)&Cp[(i0 + ty * 4 + a) * BYN + (j0 + tx * 4)] = v;
    }
}

// ---------------------------------------------------------------------------
// K2: exclusive prefix product across the NC chunks, per (i,j) pair. Tiny.
// ---------------------------------------------------------------------------
__global__ void k2_prefix()
{
    const int p = blockIdx.x * blockDim.x + threadIdx.x;
    if (p >= BXN * BYN) return;
    float run = 1.0f;
#pragma unroll
    for (int c = 0; c < NC; c++) {
        const float v = g_Cprod[c * BXN * BYN + p];
        g_Pexc[c * BXN * BYN + p] = run;
        run *= v;
    }
}

// ---------------------------------------------------------------------------
// K3: out[i,j,t] *= Pexc[chunk(t), i, j]  (streaming float4 rescale)
// ---------------------------------------------------------------------------
__global__ void k3_scale(float* __restrict__ out)
{
    const size_t v = (size_t)blockIdx.x * blockDim.x + threadIdx.x;
    const size_t e = v * 4;              // element index
    const int pair = (int)(e >> 10);     // / TN
    const int t    = (int)(e & (TN - 1));
    const int c    = t >> 4;             // / CL (CL == 16)
    const float pf = g_Pexc[c * BXN * BYN + pair];
    float4 val = ((float4*)out)[v];
    val.x *= pf; val.y *= pf; val.z *= pf; val.w *= pf;
    ((float4*)out)[v] = val;
}

extern "C" void kernel_launch(void* const* d_in, const int* in_sizes, int n_in,
                              void* d_out, int out_size)
{
    const float* X = (const float*)d_in[0];
    const float* Y = (const float*)d_in[1];
    float* out = (float*)d_out;

    dim3 g1(BXN / TI, BYN / TJ, NC);     // 4 x 4 x 64 = 1024 CTAs
    k1_chunk<<<g1, NTHREADS>>>(X, Y, out);

    k2_prefix<<<(BXN * BYN + 255) / 256, 256>>>();

    const int nvec = BXN * BYN * TN / 4; // 4M float4
    k3_scale<<<(nvec + 255) / 256, 256>>>(out);
}

// round 6
// speedup vs baseline: 1.0790x; 1.0578x over previous
#include <cuda_runtime.h>

// Problem constants (fixed shapes for this problem)
#define BXN 128     // batch of X paths (i)
#define BYN 128     // batch of Y paths (j)
#define TN  1024    // time points
#define DN  64      // path dimension
#define NSTEPS 1023 // TN-1
#define CL  8       // outputs (t values) per chunk
#define NC  128     // chunks (CL*NC == TN)
#define TI  64      // CTA tile in i
#define TJ  64      // CTA tile in j
#define NTHREADS 128
#define PAD 68      // padded smem row (floats), 16B-aligned

// Scratch (no allocation allowed -> device globals)
__device__ float g_Cprod[NC * BXN * BYN];  // per-chunk total product (8MB)
__device__ float g_Pexc [NC * BXN * BYN];  // exclusive prefix product (8MB)

// ---------------------------------------------------------------------------
// K1: per-chunk local cumulative products.
// Grid (4, NC): blockIdx.x selects the 64x64 (i,j) tile, blockIdx.y the chunk.
// CTA = 128 threads (4 warps -> all 4 SMSPs). Each thread computes an 8x4
// (i,j) sub-tile => per warp-d: 3 LDS.128 (12 crossbar cyc) vs 32 FFMA
// (16 fma cyc) -> fma-pipe bound. Each thread owns ONE full path row (threads
// 0-63: X row i0+tid, threads 64-127: Y row j0+tid-64); increments are formed
// in registers and stored transposed [d][row] into smem. Output staged 4 t's
// at a time and flushed as contiguous float4 runs.
// ---------------------------------------------------------------------------
__launch_bounds__(NTHREADS)
__global__ void k1_chunk(const float* __restrict__ X,
                         const float* __restrict__ Y,
                         float* __restrict__ out)
{
    const int i0    = (blockIdx.x & 1) * TI;
    const int j0    = (blockIdx.x >> 1) * TJ;
    const int c     = blockIdx.y;
    const int tbase = c * CL;

    __shared__ float dxs[DN][PAD];       // [d][i] increments
    __shared__ float dys[DN][PAD];       // [d][j] increments
    __shared__ float staging[4][TI*TJ];  // 4 t-slots x 4096 pairs (64KB)

    const int tid = threadIdx.x;
    const int tx  = tid & 15;   // j-group (4 j's)
    const int ty  = tid >> 4;   // i-group (8 i's)

    // loader role: one full 64-float row per thread
    const int  r    = tid & 63;
    const bool isY  = (tid >= 64);
    const float* row = (isY ? (Y + ((size_t)(j0 + r) * TN + tbase) * DN)
                            : (X + ((size_t)(i0 + r) * TN + tbase) * DN));
    float* dst = isY ? &dys[0][0] : &dxs[0][0];   // dst[d*PAD + r]

    const float STEP = 1.0f / 1023.0f;  // matches jnp.linspace delta in fp32

    float4 cur[16], nxt[16];

    // ---- prologue: rows tbase, tbase+1 -> increments for step tbase ----
#pragma unroll
    for (int q = 0; q < 16; q++) {
        float4 p0 = *(const float4*)(row + q * 4);
        float4 p1 = *(const float4*)(row + DN + q * 4);
        const int d0 = q * 4;
        dst[(d0 + 0) * PAD + r] = p1.x - p0.x;
        dst[(d0 + 1) * PAD + r] = p1.y - p0.y;
        dst[(d0 + 2) * PAD + r] = p1.z - p0.z;
        dst[(d0 + 3) * PAD + r] = p1.w - p0.w;
        cur[q] = p1;
    }
    __syncthreads();

    float K[8][4];
#pragma unroll
    for (int a = 0; a < 8; a++)
#pragma unroll
        for (int b = 0; b < 4; b++) K[a][b] = 1.0f;

#pragma unroll 1
    for (int k = 0; k < CL; k++) {
        const int s    = tbase + k;
        const int slot = k & 3;

        // ---- 1. stage current K (= out[t=s] before cross-chunk prefix) ----
#pragma unroll
        for (int a = 0; a < 8; a++) {
            float4 v = make_float4(K[a][0], K[a][1], K[a][2], K[a][3]);
            *(float4*)&staging[slot][(ty * 8 + a) * TJ + tx * 4] = v;
        }

        // ---- 2. prefetch row s+2 (consumed after the FMA phase) ----
        if (s + 2 < TN) {
            const float* rp = row + (size_t)(k + 2) * DN;
#pragma unroll
            for (int q = 0; q < 16; q++)
                nxt[q] = *(const float4*)(rp + q * 4);
        }

        // ---- 3. dot phase + scan update ----
        if (s < NSTEPS) {
            const float t1  = (s + 1 == NSTEPS) ? 1.0f : (float)(s + 1) * STEP;
            const float t0  = (float)s * STEP;
            const float inv = 1.0f / (t1 - t0);

            float acc[8][4];
#pragma unroll
            for (int a = 0; a < 8; a++)
#pragma unroll
                for (int b = 0; b < 4; b++) acc[a][b] = 0.0f;

#pragma unroll 16
            for (int d = 0; d < DN; d++) {
                const float4 yb  = *(const float4*)&dys[d][tx * 4];
                const float4 xa0 = *(const float4*)&dxs[d][ty * 8];
                const float4 xa1 = *(const float4*)&dxs[d][ty * 8 + 4];
                const float xs[8] = { xa0.x, xa0.y, xa0.z, xa0.w,
                                      xa1.x, xa1.y, xa1.z, xa1.w };
#pragma unroll
                for (int a = 0; a < 8; a++) {
                    acc[a][0] = fmaf(xs[a], yb.x, acc[a][0]);
                    acc[a][1] = fmaf(xs[a], yb.y, acc[a][1]);
                    acc[a][2] = fmaf(xs[a], yb.z, acc[a][2]);
                    acc[a][3] = fmaf(xs[a], yb.w, acc[a][3]);
                }
            }

#pragma unroll
            for (int a = 0; a < 8; a++)
#pragma unroll
                for (int b = 0; b < 4; b++)
                    K[a][b] *= fmaf(acc[a][b], inv, 1.0f);
        }

        // ---- 4. barrier: increment readers + staging writers retired ----
        __syncthreads();

        // ---- 5. flush 4 staged t-slices as contiguous float4 runs ----
        if (slot == 3) {
            const int tflush = tbase + k - 3;
#pragma unroll
            for (int w = 0; w < 32; w++) {
                int p  = tid + NTHREADS * w;   // pair index in 64x64 tile
                int pi = p >> 6, pj = p & 63;
                float4 v = make_float4(staging[0][p], staging[1][p],
                                       staging[2][p], staging[3][p]);
                *(float4*)(out + ((size_t)(i0 + pi) * BYN + (j0 + pj)) * TN + tflush) = v;
            }
        }

        // ---- 6. increments for step k+1 from prefetched row ----
        if (k + 1 < CL && s + 1 < NSTEPS) {
#pragma unroll
            for (int q = 0; q < 16; q++) {
                const int d0 = q * 4;
                dst[(d0 + 0) * PAD + r] = nxt[q].x - cur[q].x;
                dst[(d0 + 1) * PAD + r] = nxt[q].y - cur[q].y;
                dst[(d0 + 2) * PAD + r] = nxt[q].z - cur[q].z;
                dst[(d0 + 3) * PAD + r] = nxt[q].w - cur[q].w;
                cur[q] = nxt[q];
            }
        }

        // ---- 7. barrier: increments visible; staging safe to overwrite ----
        __syncthreads();
    }

    // chunk-total product (for cross-chunk prefix)
    float* Cp = g_Cprod + (size_t)c * (BXN * BYN);
#pragma unroll
    for (int a = 0; a < 8; a++) {
        float4 v = make_float4(K[a][0], K[a][1], K[a][2], K[a][3]);
        *(float4*)&Cp[(i0 + ty * 8 + a) * BYN + (j0 + tx * 4)] = v;
    }
}

// ---------------------------------------------------------------------------
// K2: exclusive prefix product across the NC chunks, per (i,j) pair. Tiny.
// ---------------------------------------------------------------------------
__global__ void k2_prefix()
{
    const int p = blockIdx.x * blockDim.x + threadIdx.x;
    if (p >= BXN * BYN) return;
    float run = 1.0f;
#pragma unroll
    for (int c = 0; c < NC; c++) {
        const float v = g_Cprod[c * BXN * BYN + p];
        g_Pexc[c * BXN * BYN + p] = run;
        run *= v;
    }
}

// ---------------------------------------------------------------------------
// K3: out[i,j,t] *= Pexc[chunk(t), i, j]  (streaming float4 rescale)
// ---------------------------------------------------------------------------
__global__ void k3_scale(float* __restrict__ out)
{
    const size_t v = (size_t)blockIdx.x * blockDim.x + threadIdx.x;
    const size_t e = v * 4;              // element index
    const int pair = (int)(e >> 10);     // / TN
    const int t    = (int)(e & (TN - 1));
    const int c    = t >> 3;             // / CL (CL == 8)
    const float pf = g_Pexc[c * BXN * BYN + pair];
    float4 val = ((float4*)out)[v];
    val.x *= pf; val.y *= pf; val.z *= pf; val.w *= pf;
    ((float4*)out)[v] = val;
}

extern "C" void kernel_launch(void* const* d_in, const int* in_sizes, int n_in,
                              void* d_out, int out_size)
{
    const float* X = (const float*)d_in[0];
    const float* Y = (const float*)d_in[1];
    float* out = (float*)d_out;

    dim3 g1(4, NC);                      // 4 tiles x 128 chunks = 512 CTAs
    k1_chunk<<<g1, NTHREADS>>>(X, Y, out);

    k2_prefix<<<(BXN * BYN + 255) / 256, 256>>>();

    const int nvec = BXN * BYN * TN / 4; // 4M float4
    k3_scale<<<(nvec + 255) / 256, 256>>>(out);
}